// round 14
// baseline (speedup 1.0000x reference)
#include <cuda_runtime.h>

// PhysicsEngine: B=8, NL=128, NP=8192 pairwise soft-core energy -> 3 scalars/batch.
// R13 structure with the 40-reg cap lifted (launch_bounds(256,4) -> 64 regs) so
// loop-invariant FP constants stay register-resident instead of being
// rematerialized via MOVs every iteration (the observed 17-op/iter alu anomaly).

#define NB 8
#define NL 128
#define NP 8192
#define BCHUNK 64             // protein atoms per block
#define HCHUNK 32             // per half
#define NCHUNK (NP / BCHUNK)  // 128 blocks per batch
#define NT 256

__device__ float g_part[NB * NCHUNK * 5];
__device__ unsigned g_count = 0;

__device__ __forceinline__ float f_sqrt(float x) {
    float y; asm("sqrt.approx.f32 %0,%1;" : "=f"(y) : "f"(x)); return y;
}
__device__ __forceinline__ float f_rsq(float x) {
    float y; asm("rsqrt.approx.f32 %0,%1;" : "=f"(y) : "f"(x)); return y;
}
__device__ __forceinline__ float f_ex2(float x) {
    float y; asm("ex2.approx.f32 %0,%1;" : "=f"(y) : "f"(x)); return y;
}
__device__ __forceinline__ float f_rcp(float x) {
    float y; asm("rcp.approx.f32 %0,%1;" : "=f"(y) : "f"(x)); return y;
}

__global__ __launch_bounds__(NT, 4) void pe_fused_kernel(
    const float* __restrict__ pos_L, const float* __restrict__ pos_P,
    const float* __restrict__ q_L,   const float* __restrict__ q_P,
    const float* __restrict__ x_L,   const float* __restrict__ x_P,
    const float* __restrict__ vdw_radii, const float* __restrict__ epsilon,
    float* __restrict__ out)
{
    const int c = blockIdx.x;                 // protein block-chunk (64 atoms)
    const int b = blockIdx.y;                 // batch
    const int tid = threadIdx.x;
    const int l = tid & (NL - 1);             // ligand index
    const int half = tid >> 7;                // which 32-atom half

    __shared__ float4 sp[BCHUNK];             // protein x, y, z, q
    __shared__ float2 sr[BCHUNK];             // protein radius, x0
    __shared__ float sxl[NL * 9];             // ligand type probs (coalesced)
    __shared__ float spl[NL * 3];             // ligand positions (coalesced)

    // ---- coalesced staging over all 256 threads ----
    {
        const float* gx = x_L + (size_t)b * NL * 9;
        for (int i = tid; i < NL * 9; i += NT) sxl[i] = gx[i];
        const float* gp = pos_L + (size_t)b * NL * 3;
        if (tid < NL * 3 - NT) spl[tid + NT] = gp[tid + NT];
        spl[tid] = gp[tid];                     // tid < 384 always (NT=256)
    }
    if (tid < BCHUNK) {
        const int p = c * BCHUNK + tid;
        const float4 xp = *(const float4*)(x_P + ((size_t)b * NP + p) * 4);
        float4 v;
        v.x = pos_P[((size_t)b * NP + p) * 3 + 0];
        v.y = pos_P[((size_t)b * NP + p) * 3 + 1];
        v.z = pos_P[((size_t)b * NP + p) * 3 + 2];
        v.w = q_P[b * NP + p];
        sp[tid] = v;
        float2 r;
        r.x = fmaf(xp.x, 1.7f, fmaf(xp.y, 1.55f, fmaf(xp.z, 1.52f, xp.w * 1.8f)));
        r.y = xp.x;
        sr[tid] = r;
    }
    const float ql83 = 83.015f * q_L[b * NL + l];

    __syncthreads();

    // ---- per-ligand derived quantities (from SMEM) ----
    float radL = 0.f, epsd = 0.f;
#pragma unroll
    for (int k = 0; k < 9; k++) {
        float x = sxl[l * 9 + k];
        radL = fmaf(x, vdw_radii[k], radL);
        epsd = fmaf(x, epsilon[k],   epsd);
    }
    epsd = fmaxf(epsd, 0.f);
    const float c4  = 4.f * sqrtf(fmaf(epsd, 0.15f, 1e-8f));   // 4*eps_ij
    const float lx  = spl[l * 3 + 0];
    const float ly  = spl[l * 3 + 1];
    const float lz  = spl[l * 3 + 2];
    const float xl0 = sxl[l * 9 + 0];

    // Accumulators (per-thread constants hoisted; ex-term linearized out):
    float s_elec = 0.f, s_vdw = 0.f, s_mask = 0.f, s_hsar = 0.f,
          s_pauli = 0.f, s_ghost = 0.f;

    const int jbase = half * HCHUNK;
    float4 pcur = sp[jbase];
    float2 rcur = sr[jbase];

#pragma unroll
    for (int j = 0; j < HCHUNK; j++) {
        const float4 p = pcur;
        const float2 r = rcur;
        if (j + 1 < HCHUNK) {                 // prefetch next iteration's operands
            pcur = sp[jbase + j + 1];
            rcur = sr[jbase + j + 1];
        }

        const float dx = lx - p.x;
        const float dy = ly - p.y;
        const float dz = lz - p.z;
        const float t = fmaf(dx, dx, fmaf(dy, dy, fmaf(dz, dz, 1e-8f)));

        const float dist = f_sqrt(t);                 // sqrt(dsq + 1e-8)

        const float sigma = radL + r.x;
        const float ssq   = fmaf(sigma, sigma, t);
        const float invs  = f_rsq(ssq);               // 1/soft_dist

        // ratio = sigma/soft_dist <= 1 always (min(.,5) never binds)
        const float ratio = sigma * invs;
        const float r2 = ratio * ratio;
        const float r6 = r2 * r2 * r2;
        const float evr = c4 * fmaf(r6, r6, -r6);     // e_vdw_raw in [-0.52, 0]

        // em = exp(2*dist - 24); far away em=inf -> R=0, mask=0 (matches ref)
        const float em = f_ex2(fmaf(dist, 2.8853900817779268f, -34.624680981335122f));

        // A = 1 + dsq^2/256; single RCP: R = 1/(A*(1+em)) = hsa*mask; mask = R*A
        const float A    = fmaf(t * t, 0.00390625f, 1.f);
        const float R    = f_rcp(A * (1.f + em));
        const float mask = R * A;

        s_elec = fmaf(p.w * invs, mask, s_elec);
        s_vdw  = fmaf(evr, mask, s_vdw);
        s_mask += mask;
        s_hsar = fmaf(r.y, R, s_hsar);

        const float ov = fmaxf(fmaf(sigma, 0.6f, -dist), 0.f);
        s_pauli = fmaf(ov, ov, s_pauli);
        const float gh = fmaxf(0.5f - dist, 0.f);
        s_ghost = fmaf(gh, gh, s_ghost);
    }

    // ---- fold per-thread constants, then deterministic block reduction ----
    float v[5];
    v[0] = fmaf(ql83, s_elec, s_vdw);   // Sum (e_elec+evr)*mask  (exact log branch)
    v[1] = s_mask - s_vdw;              // Sum (1-evr)*mask -> ex sum = e^-10 * v1
    v[2] = xl0 * s_hsar;                // Sum mask_cc * hsa_term * dist_mask
    v[3] = s_pauli;
    v[4] = s_ghost;
#pragma unroll
    for (int k = 0; k < 5; k++) {
#pragma unroll
        for (int off = 16; off > 0; off >>= 1)
            v[k] += __shfl_down_sync(0xffffffffu, v[k], off);
    }
    __shared__ float wred[8][5];
    const int wid = tid >> 5, lane = tid & 31;
    if (lane == 0) {
#pragma unroll
        for (int k = 0; k < 5; k++) wred[wid][k] = v[k];
    }
    __syncthreads();
    if (tid == 0) {
#pragma unroll
        for (int k = 0; k < 5; k++) {
            float s = 0.f;
#pragma unroll
            for (int w = 0; w < 8; w++) s += wred[w][k];
            g_part[(b * NCHUNK + c) * 5 + k] = s;
        }
    }

    // ---- last block finalizes (threadfence reduction pattern) ----
    __shared__ bool is_last;
    if (tid == 0) {
        __threadfence();
        unsigned done = atomicAdd(&g_count, 1u);
        is_last = (done == (unsigned)(gridDim.x * gridDim.y) - 1u);
    }
    __syncthreads();
    if (!is_last) return;

    __shared__ float acc[NB][5];
    for (int task = wid; task < NB * 5; task += 8) {
        const int tb = task / 5, tk = task % 5;
        float s = 0.f;
#pragma unroll 4
        for (int cc = lane; cc < NCHUNK; cc += 32)
            s += g_part[(tb * NCHUNK + cc) * 5 + tk];
#pragma unroll
        for (int off = 16; off > 0; off >>= 1)
            s += __shfl_down_sync(0xffffffffu, s, off);
        if (lane == 0) acc[tb][tk] = s;
    }
    __syncthreads();
    if (tid < NB) {
        const int w = tid;
        const float s_l = acc[w][0], s_x = acc[w][1], s_h = acc[w][2],
                    s_p = acc[w][3], s_g = acc[w][4];
        const float e_ex    = 4.5399929762484854e-05f * s_x;  // e^-10 * Sum (1-evr)*mask
        const float e_hsa5  = -2.5f * s_h;                    // 5 * (-0.5 * s_hsa)
        const float e_pauli = 11.920292202211755f * s_p;      // 100*sigmoid(-2)
        const float e_ghost = 500.f * s_g;

        out[w] = (s_l + e_ex) + e_hsa5 + e_pauli + e_ghost;   // e_raw

        const float e_hard = fminf(e_pauli + e_ghost, 10000.f);
        out[8 + w] = e_hard;

        float log_soft = s_l + e_hsa5;                        // clip(evr)=evr exactly
        float e_soft_final = fminf(fmaxf(log_soft, -500.f), 5000.f);
        out[16 + w] = fminf(e_soft_final + e_hard, 1000000.f);
    }
    if (tid == 0) g_count = 0;   // reset for next graph replay
}

extern "C" void kernel_launch(void* const* d_in, const int* in_sizes, int n_in,
                              void* d_out, int out_size)
{
    const float* pos_L = (const float*)d_in[0];
    const float* pos_P = (const float*)d_in[1];
    const float* q_L   = (const float*)d_in[2];
    const float* q_P   = (const float*)d_in[3];
    const float* x_L   = (const float*)d_in[4];
    const float* x_P   = (const float*)d_in[5];
    const float* vdw   = (const float*)d_in[6];
    const float* eps   = (const float*)d_in[7];

    dim3 grid(NCHUNK, NB);
    pe_fused_kernel<<<grid, NT>>>(pos_L, pos_P, q_L, q_P, x_L, x_P, vdw, eps,
                                  (float*)d_out);
}

// round 15
// speedup vs baseline: 1.0986x; 1.0986x over previous
#include <cuda_runtime.h>

// PhysicsEngine: B=8, NL=128, NP=8192 pairwise soft-core energy -> 3 scalars/batch.
// ROLE SWAP: thread = protein atom (cheap per-thread setup), ligand params
// (expensive 9-dot+sqrt) computed once per block by 32 threads into SMEM.
// 1024 blocks x 256 threads, 32 ligand-iterations/thread, fused finalize.

#define NB 8
#define NL 128
#define NP 8192
#define ACHUNK 256            // protein atoms per block (= NT)
#define LQ 32                 // ligands per block (quarter)
#define NCHUNK ((NP / ACHUNK) * (NL / LQ))   // 32 * 4 = 128 partials per batch
#define NT 256

__device__ float g_part[NB * NCHUNK * 5];
__device__ unsigned g_count = 0;

__device__ __forceinline__ float f_sqrt(float x) {
    float y; asm("sqrt.approx.f32 %0,%1;" : "=f"(y) : "f"(x)); return y;
}
__device__ __forceinline__ float f_rsq(float x) {
    float y; asm("rsqrt.approx.f32 %0,%1;" : "=f"(y) : "f"(x)); return y;
}
__device__ __forceinline__ float f_ex2(float x) {
    float y; asm("ex2.approx.f32 %0,%1;" : "=f"(y) : "f"(x)); return y;
}
__device__ __forceinline__ float f_rcp(float x) {
    float y; asm("rcp.approx.f32 %0,%1;" : "=f"(y) : "f"(x)); return y;
}

__global__ __launch_bounds__(NT, 6) void pe_fused_kernel(
    const float* __restrict__ pos_L, const float* __restrict__ pos_P,
    const float* __restrict__ q_L,   const float* __restrict__ q_P,
    const float* __restrict__ x_L,   const float* __restrict__ x_P,
    const float* __restrict__ vdw_radii, const float* __restrict__ epsilon,
    float* __restrict__ out)
{
    const int ca = blockIdx.x >> 2;           // protein atom chunk (0..31)
    const int qd = blockIdx.x & 3;            // ligand quarter (0..3)
    const int b  = blockIdx.y;                // batch
    const int tid = threadIdx.x;

    __shared__ float4 sL1[LQ];                // lx, ly, lz, 83.015*qL
    __shared__ float4 sL2[LQ];                // radL, c4, x0L, (pad)

    // ---- ligand staging: 32 threads each compute one ligand's derived params ----
    if (tid < LQ) {
        const int lg = qd * LQ + tid;
        const float* xl = x_L + ((size_t)b * NL + lg) * 9;
        float radL = 0.f, epsd = 0.f;
#pragma unroll
        for (int k = 0; k < 9; k++) {
            const float x = xl[k];
            radL = fmaf(x, vdw_radii[k], radL);
            epsd = fmaf(x, epsilon[k],   epsd);
        }
        epsd = fmaxf(epsd, 0.f);
        float4 v1, v2;
        v1.x = pos_L[((size_t)b * NL + lg) * 3 + 0];
        v1.y = pos_L[((size_t)b * NL + lg) * 3 + 1];
        v1.z = pos_L[((size_t)b * NL + lg) * 3 + 2];
        v1.w = 83.015f * q_L[b * NL + lg];
        v2.x = radL;
        v2.y = 4.f * sqrtf(fmaf(epsd, 0.15f, 1e-8f));  // 4*eps_ij
        v2.z = xl[0];
        v2.w = 0.f;
        sL1[tid] = v1;
        sL2[tid] = v2;
    }

    // ---- per-thread protein atom (cheap setup) ----
    const int p = ca * ACHUNK + tid;
    const float4 xp = *(const float4*)(x_P + ((size_t)b * NP + p) * 4);
    const float radP = fmaf(xp.x, 1.7f, fmaf(xp.y, 1.55f, fmaf(xp.z, 1.52f, xp.w * 1.8f)));
    const float x0P  = xp.x;
    const float px = pos_P[((size_t)b * NP + p) * 3 + 0];
    const float py = pos_P[((size_t)b * NP + p) * 3 + 1];
    const float pz = pos_P[((size_t)b * NP + p) * 3 + 2];
    const float qP = q_P[b * NP + p];

    __syncthreads();

    // Accumulators (per-thread constants qP/x0P hoisted; ex-term linearized out):
    float s_elec = 0.f, s_vdw = 0.f, s_mask = 0.f, s_hsar = 0.f,
          s_pauli = 0.f, s_ghost = 0.f;

#pragma unroll
    for (int j = 0; j < LQ; j++) {
        const float4 L1 = sL1[j];             // broadcast LDS.128
        const float4 L2 = sL2[j];

        const float dx = L1.x - px;
        const float dy = L1.y - py;
        const float dz = L1.z - pz;
        const float t = fmaf(dx, dx, fmaf(dy, dy, fmaf(dz, dz, 1e-8f)));

        const float dist = f_sqrt(t);                 // sqrt(dsq + 1e-8)

        const float sigma = radP + L2.x;
        const float ssq   = fmaf(sigma, sigma, t);
        const float invs  = f_rsq(ssq);               // 1/soft_dist

        // ratio = sigma/soft_dist <= 1 always (min(.,5) never binds)
        const float ratio = sigma * invs;
        const float r2 = ratio * ratio;
        const float r6 = r2 * r2 * r2;
        const float evr = L2.y * fmaf(r6, r6, -r6);   // e_vdw_raw in [-0.52, 0]

        // em = exp(2*dist - 24); far away em=inf -> R=0, mask=0 (matches ref)
        const float em = f_ex2(fmaf(dist, 2.8853900817779268f, -34.624680981335122f));

        // A = 1 + dsq^2/256; single RCP: R = 1/(A*(1+em)) = hsa*mask; mask = R*A
        const float A    = fmaf(t * t, 0.00390625f, 1.f);
        const float R    = f_rcp(A * (1.f + em));
        const float mask = R * A;

        s_elec = fmaf(L1.w * invs, mask, s_elec);     // 83.015*qL * invs * mask
        s_vdw  = fmaf(evr, mask, s_vdw);
        s_mask += mask;
        s_hsar = fmaf(L2.z, R, s_hsar);               // x0L * hsa * mask

        const float ov = fmaxf(fmaf(sigma, 0.6f, -dist), 0.f);
        s_pauli = fmaf(ov, ov, s_pauli);
        const float gh = fmaxf(0.5f - dist, 0.f);
        s_ghost = fmaf(gh, gh, s_ghost);
    }

    // ---- fold per-thread constants, then deterministic block reduction ----
    float v[5];
    v[0] = fmaf(qP, s_elec, s_vdw);     // Sum (e_elec+evr)*mask  (exact log branch)
    v[1] = s_mask - s_vdw;              // Sum (1-evr)*mask -> ex sum = e^-10 * v1
    v[2] = x0P * s_hsar;                // Sum mask_cc * hsa_term * dist_mask
    v[3] = s_pauli;
    v[4] = s_ghost;
#pragma unroll
    for (int k = 0; k < 5; k++) {
#pragma unroll
        for (int off = 16; off > 0; off >>= 1)
            v[k] += __shfl_down_sync(0xffffffffu, v[k], off);
    }
    __shared__ float wred[8][5];
    const int wid = tid >> 5, lane = tid & 31;
    if (lane == 0) {
#pragma unroll
        for (int k = 0; k < 5; k++) wred[wid][k] = v[k];
    }
    __syncthreads();
    if (tid == 0) {
#pragma unroll
        for (int k = 0; k < 5; k++) {
            float s = 0.f;
#pragma unroll
            for (int w = 0; w < 8; w++) s += wred[w][k];
            g_part[(b * NCHUNK + (ca * 4 + qd)) * 5 + k] = s;
        }
    }

    // ---- last block finalizes (threadfence reduction pattern) ----
    __shared__ bool is_last;
    if (tid == 0) {
        __threadfence();
        unsigned done = atomicAdd(&g_count, 1u);
        is_last = (done == (unsigned)(gridDim.x * gridDim.y) - 1u);
    }
    __syncthreads();
    if (!is_last) return;

    __shared__ float acc[NB][5];
    for (int task = wid; task < NB * 5; task += 8) {
        const int tb = task / 5, tk = task % 5;
        float s = 0.f;
#pragma unroll 4
        for (int cc = lane; cc < NCHUNK; cc += 32)
            s += g_part[(tb * NCHUNK + cc) * 5 + tk];
#pragma unroll
        for (int off = 16; off > 0; off >>= 1)
            s += __shfl_down_sync(0xffffffffu, s, off);
        if (lane == 0) acc[tb][tk] = s;
    }
    __syncthreads();
    if (tid < NB) {
        const int w = tid;
        const float s_l = acc[w][0], s_x = acc[w][1], s_h = acc[w][2],
                    s_p = acc[w][3], s_g = acc[w][4];
        const float e_ex    = 4.5399929762484854e-05f * s_x;  // e^-10 * Sum (1-evr)*mask
        const float e_hsa5  = -2.5f * s_h;                    // 5 * (-0.5 * s_hsa)
        const float e_pauli = 11.920292202211755f * s_p;      // 100*sigmoid(-2)
        const float e_ghost = 500.f * s_g;

        out[w] = (s_l + e_ex) + e_hsa5 + e_pauli + e_ghost;   // e_raw

        const float e_hard = fminf(e_pauli + e_ghost, 10000.f);
        out[8 + w] = e_hard;

        float log_soft = s_l + e_hsa5;                        // clip(evr)=evr exactly
        float e_soft_final = fminf(fmaxf(log_soft, -500.f), 5000.f);
        out[16 + w] = fminf(e_soft_final + e_hard, 1000000.f);
    }
    if (tid == 0) g_count = 0;   // reset for next graph replay
}

extern "C" void kernel_launch(void* const* d_in, const int* in_sizes, int n_in,
                              void* d_out, int out_size)
{
    const float* pos_L = (const float*)d_in[0];
    const float* pos_P = (const float*)d_in[1];
    const float* q_L   = (const float*)d_in[2];
    const float* q_P   = (const float*)d_in[3];
    const float* x_L   = (const float*)d_in[4];
    const float* x_P   = (const float*)d_in[5];
    const float* vdw   = (const float*)d_in[6];
    const float* eps   = (const float*)d_in[7];

    dim3 grid((NP / ACHUNK) * (NL / LQ), NB);   // (128, 8)
    pe_fused_kernel<<<grid, NT>>>(pos_L, pos_P, q_L, q_P, x_L, x_P, vdw, eps,
                                  (float*)d_out);
}